// round 4
// baseline (speedup 1.0000x reference)
#include <cuda_runtime.h>

// DerivativeNet forward, direction='x'
// u:    [B=16, C=2, H=1024, W=1024] float32
// mask: [B=16, 1,   H=1024, W=1024] float32 (values exactly 0.0 or 1.0)
// out = eroded*central + edge1*forward + edge2*backward (zero-padded stencils, h=0.01)
//
// 128 threads/row, 8 elements/thread (2x float4 per array). Halos via warp
// shuffles; cross-warp edges + scan partials via ~64B of shared. All offsets
// 32-bit.

#define WIDTH   1024
#define HEIGHT  1024
#define INV_H   100.0f
#define INV_2H  50.0f
#define NT      128

__device__ __forceinline__ float delem(float um1, float ui, float up1,
                                       bool er, bool e1, bool e2)
{
    float r = er ? (up1 - um1) * INV_2H : 0.0f;
    r += e1 ? (up1 - ui) * INV_H : 0.0f;
    r += e2 ? (ui - um1) * INV_H : 0.0f;
    return r;
}

__global__ __launch_bounds__(NT, 6)
void dnet_kernel(const float* __restrict__ u,
                 const float* __restrict__ mask,
                 float* __restrict__ out)
{
    const int tid  = threadIdx.x;
    const int lane = tid & 31;
    const int wid  = tid >> 5;               // 0..3

    __shared__ int   wsums[4];
    __shared__ int   em_last[4],  em_first[4];
    __shared__ float ea_last[4],  ea_first[4];
    __shared__ float ec_last[4],  ec_first[4];

    const unsigned row   = blockIdx.x;                    // b*HEIGHT + y
    const unsigned b     = row >> 10;
    const unsigned y     = row & (HEIGHT - 1);
    const unsigned base0 = ((b * 2u) << 20) | (y << 10);  // u channel 0 (elements)
    const unsigned base1 = base0 + (1u << 20);            // u channel 1

    // float4-granular row pointers
    const float4* m4p = reinterpret_cast<const float4*>(mask) + ((row << 10) >> 2);
    const float4* a4p = reinterpret_cast<const float4*>(u) + (base0 >> 2);
    const float4* c4p = reinterpret_cast<const float4*>(u) + (base1 >> 2);

    const int q = tid * 2;
    // ---- 6 independent vector loads up front (MLP=6) ----
    const float4 m_lo = m4p[q],     m_hi = m4p[q + 1];
    const float4 a_lo = a4p[q],     a_hi = a4p[q + 1];
    const float4 c_lo = c4p[q],     c_hi = c4p[q + 1];

    const int b0 = (m_lo.x != 0.0f), b1 = (m_lo.y != 0.0f),
              b2 = (m_lo.z != 0.0f), b3 = (m_lo.w != 0.0f),
              b4 = (m_hi.x != 0.0f), b5 = (m_hi.y != 0.0f),
              b6 = (m_hi.z != 0.0f), b7 = (m_hi.w != 0.0f);
    const int tsum = b0 + b1 + b2 + b3 + b4 + b5 + b6 + b7;

    // ---- warp-inclusive scan of per-thread counts ----
    int v = tsum;
    #pragma unroll
    for (int o = 1; o < 32; o <<= 1) {
        int n = __shfl_up_sync(0xffffffffu, v, o);
        if (lane >= o) v += n;
    }

    // ---- in-warp halo exchange ----
    int   ml = __shfl_up_sync  (0xffffffffu, b7,     1);
    float al = __shfl_up_sync  (0xffffffffu, a_hi.w, 1);
    float cl = __shfl_up_sync  (0xffffffffu, c_hi.w, 1);
    int   mr = __shfl_down_sync(0xffffffffu, b0,     1);
    float ar = __shfl_down_sync(0xffffffffu, a_lo.x, 1);
    float cr = __shfl_down_sync(0xffffffffu, c_lo.x, 1);

    // ---- cross-warp edges + scan partials ----
    if (lane == 31) {
        wsums[wid] = v;
        em_last[wid] = b7; ea_last[wid] = a_hi.w; ec_last[wid] = c_hi.w;
    }
    if (lane == 0) {
        em_first[wid] = b0; ea_first[wid] = a_lo.x; ec_first[wid] = c_lo.x;
    }
    __syncthreads();

    int excl  = v - tsum;
    int total = 0;
    #pragma unroll
    for (int w = 0; w < 4; w++) {
        const int x = wsums[w];
        if (w < wid) excl += x;
        total += x;
    }

    if (lane == 0) {
        if (wid > 0) { ml = em_last[wid-1]; al = ea_last[wid-1]; cl = ec_last[wid-1]; }
        else         { ml = 0; al = 0.0f; cl = 0.0f; }
    }
    if (lane == 31) {
        if (wid < 3) { mr = em_first[wid+1]; ar = ea_first[wid+1]; cr = ec_first[wid+1]; }
        else         { mr = 0; ar = 0.0f; cr = 0.0f; }
    }

    // ---- per-element conditions (registers only) ----
    const int p0 = excl + b0, p1 = p0 + b1, p2 = p1 + b2, p3 = p2 + b3,
              p4 = p3 + b4,  p5 = p4 + b5, p6 = p5 + b6, p7 = p6 + b7;

    const bool er0 = ml && b0 && b1;
    const bool er1 = b0 && b1 && b2;
    const bool er2 = b1 && b2 && b3;
    const bool er3 = b2 && b3 && b4;
    const bool er4 = b3 && b4 && b5;
    const bool er5 = b4 && b5 && b6;
    const bool er6 = b5 && b6 && b7;
    const bool er7 = b6 && b7 && mr;

    const bool e10 = (p0 == 1), e11 = (p1 == 1), e12 = (p2 == 1), e13 = (p3 == 1),
               e14 = (p4 == 1), e15 = (p5 == 1), e16 = (p6 == 1), e17 = (p7 == 1);
    const bool e20 = b0 && (p0 == total), e21 = b1 && (p1 == total),
               e22 = b2 && (p2 == total), e23 = b3 && (p3 == total),
               e24 = b4 && (p4 == total), e25 = b5 && (p5 == total),
               e26 = b6 && (p6 == total), e27 = b7 && (p7 == total);

    float4* o4a = reinterpret_cast<float4*>(out) + (base0 >> 2);
    float4* o4c = reinterpret_cast<float4*>(out) + (base1 >> 2);

    // ---- channel 0 ----
    {
        float4 rlo, rhi;
        rlo.x = delem(al,     a_lo.x, a_lo.y, er0, e10, e20);
        rlo.y = delem(a_lo.x, a_lo.y, a_lo.z, er1, e11, e21);
        rlo.z = delem(a_lo.y, a_lo.z, a_lo.w, er2, e12, e22);
        rlo.w = delem(a_lo.z, a_lo.w, a_hi.x, er3, e13, e23);
        rhi.x = delem(a_lo.w, a_hi.x, a_hi.y, er4, e14, e24);
        rhi.y = delem(a_hi.x, a_hi.y, a_hi.z, er5, e15, e25);
        rhi.z = delem(a_hi.y, a_hi.z, a_hi.w, er6, e16, e26);
        rhi.w = delem(a_hi.z, a_hi.w, ar,     er7, e17, e27);
        o4a[q]     = rlo;
        o4a[q + 1] = rhi;
    }

    // ---- channel 1 ----
    {
        float4 rlo, rhi;
        rlo.x = delem(cl,     c_lo.x, c_lo.y, er0, e10, e20);
        rlo.y = delem(c_lo.x, c_lo.y, c_lo.z, er1, e11, e21);
        rlo.z = delem(c_lo.y, c_lo.z, c_lo.w, er2, e12, e22);
        rlo.w = delem(c_lo.z, c_lo.w, c_hi.x, er3, e13, e23);
        rhi.x = delem(c_lo.w, c_hi.x, c_hi.y, er4, e14, e24);
        rhi.y = delem(c_hi.x, c_hi.y, c_hi.z, er5, e15, e25);
        rhi.z = delem(c_hi.y, c_hi.z, c_hi.w, er6, e16, e26);
        rhi.w = delem(c_hi.z, c_hi.w, cr,     er7, e17, e27);
        o4c[q]     = rlo;
        o4c[q + 1] = rhi;
    }
}

extern "C" void kernel_launch(void* const* d_in, const int* in_sizes, int n_in,
                              void* d_out, int out_size)
{
    const float* u    = (const float*)d_in[0];
    const float* mask = (const float*)d_in[1];
    float* o = (float*)d_out;

    const int nrows = 16 * HEIGHT;   // 16384 blocks, one per (b, y) row
    dnet_kernel<<<nrows, NT>>>(u, mask, o);
}

// round 5
// speedup vs baseline: 1.0175x; 1.0175x over previous
#include <cuda_runtime.h>

// DerivativeNet forward, direction='x'
// u:    [B=16, C=2, H=1024, W=1024] float32
// mask: [B=16, 1,   H=1024, W=1024] float32 (values exactly 0.0 or 1.0)
// out = eroded*central + edge1*forward + edge2*backward (zero-padded, h=0.01)
//
// edge1 = (cumsum==1)          == interval [first_set, second_set)
// edge2 = (cumsum==max)&mask   == {last_set}
// -> only 3 row-global indices needed; no prefix scan.

#define HEIGHT  1024
#define INV_H   100.0f
#define INV_2H  50.0f
#define NT      256
#define BIG     0x7fffffff

__device__ __forceinline__ float delem(float um1, float ui, float up1,
                                       bool er, bool e1, bool e2)
{
    float r = er ? (up1 - um1) * INV_2H : 0.0f;
    r += e1 ? (up1 - ui) * INV_H : 0.0f;
    r += e2 ? (ui - um1) * INV_H : 0.0f;
    return r;
}

__global__ __launch_bounds__(NT, 6)
void dnet_kernel(const float* __restrict__ u,
                 const float* __restrict__ mask,
                 float* __restrict__ out)
{
    const int tid  = threadIdx.x;
    const int lane = tid & 31;
    const int wid  = tid >> 5;               // 0..7

    __shared__ int wfs[8], wss[8], wls[8];               // per-warp first/second/last
    __shared__ int em_last[8], em_first[8];              // warp-edge mask bits
    __shared__ float ea_last[8], ea_first[8];            // warp-edge u ch0
    __shared__ float ec_last[8], ec_first[8];            // warp-edge u ch1

    const unsigned row   = blockIdx.x;                   // b*HEIGHT + y
    const unsigned b     = row >> 10;
    const unsigned y     = row & (HEIGHT - 1);
    const unsigned base0 = ((b * 2u) << 20) | (y << 10); // u channel 0, elements
    const unsigned base1 = base0 + (1u << 20);           // u channel 1

    const float4* m4p = reinterpret_cast<const float4*>(mask) + ((row << 10) >> 2);
    const float4* a4p = reinterpret_cast<const float4*>(u) + (base0 >> 2);
    const float4* c4p = reinterpret_cast<const float4*>(u) + (base1 >> 2);

    // ---- 3 streaming vector loads up front ----
    const float4 m4 = __ldcs(m4p + tid);
    const float4 a4 = __ldcs(a4p + tid);
    const float4 c4 = __ldcs(c4p + tid);

    const int b0 = (m4.x != 0.0f), b1 = (m4.y != 0.0f),
              b2 = (m4.z != 0.0f), b3 = (m4.w != 0.0f);
    const int mbits = b0 | (b1 << 1) | (b2 << 2) | (b3 << 3);

    // ---- warp-level first/second/last set positions (no scan) ----
    const unsigned full = 0xffffffffu;
    const unsigned nz  = __ballot_sync(full, mbits != 0);
    const unsigned nz2 = nz & (nz - 1);

    const int t1 = nz  ? (__ffs(nz)  - 1) : 0;
    const int t2 = nz2 ? (__ffs(nz2) - 1) : 0;
    const int tL = nz  ? (31 - __clz(nz)) : 0;

    const int mt1 = __shfl_sync(full, mbits, t1);
    const int mt2 = __shfl_sync(full, mbits, t2);
    const int mtL = __shfl_sync(full, mbits, tL);

    const int wbase = wid << 7;              // warp covers 128 elements
    int wf = BIG, ws = BIG, wl = -1;
    if (nz) {
        wf = wbase + (t1 << 2) + (__ffs(mt1) - 1);
        const int m1b = mt1 & (mt1 - 1);     // drop lowest bit of first thread's mask
        if (m1b)      ws = wbase + (t1 << 2) + (__ffs(m1b) - 1);
        else if (nz2) ws = wbase + (t2 << 2) + (__ffs(mt2) - 1);
        wl = wbase + (tL << 2) + (31 - __clz(mtL));
    }

    // ---- in-warp halo exchange ----
    int   ml = __shfl_up_sync  (full, b3,   1);
    float al = __shfl_up_sync  (full, a4.w, 1);
    float cl = __shfl_up_sync  (full, c4.w, 1);
    int   mr = __shfl_down_sync(full, b0,   1);
    float ar = __shfl_down_sync(full, a4.x, 1);
    float cr = __shfl_down_sync(full, c4.x, 1);

    if (lane == 31) {
        wfs[wid] = wf; wss[wid] = ws; wls[wid] = wl;
        em_last[wid] = b3; ea_last[wid] = a4.w; ec_last[wid] = c4.w;
    }
    if (lane == 0) {
        em_first[wid] = b0; ea_first[wid] = a4.x; ec_first[wid] = c4.x;
    }
    __syncthreads();

    // ---- merge per-warp indices (warps cover disjoint increasing ranges) ----
    int f1 = BIG, f2 = BIG, lastp = -1;
    #pragma unroll
    for (int w = 0; w < 8; w++) {
        const int a = wfs[w];                // broadcast LDS
        if (a != BIG) {
            if (f1 == BIG)      { f1 = a; f2 = wss[w]; }
            else if (f2 == BIG) { f2 = a; }
            lastp = wls[w];
        }
    }

    // ---- fix halos at warp boundaries (zero padding at row ends) ----
    if (lane == 0) {
        if (wid > 0) { ml = em_last[wid-1]; al = ea_last[wid-1]; cl = ec_last[wid-1]; }
        else         { ml = 0; al = 0.0f; cl = 0.0f; }
    }
    if (lane == 31) {
        if (wid < 7) { mr = em_first[wid+1]; ar = ea_first[wid+1]; cr = ec_first[wid+1]; }
        else         { mr = 0; ar = 0.0f; cr = 0.0f; }
    }

    // ---- per-element conditions ----
    const int i0 = tid << 2;
    const bool e10 = (i0     >= f1) & (i0     < f2);
    const bool e11 = (i0 + 1 >= f1) & (i0 + 1 < f2);
    const bool e12 = (i0 + 2 >= f1) & (i0 + 2 < f2);
    const bool e13 = (i0 + 3 >= f1) & (i0 + 3 < f2);
    const bool e20 = (i0     == lastp);
    const bool e21 = (i0 + 1 == lastp);
    const bool e22 = (i0 + 2 == lastp);
    const bool e23 = (i0 + 3 == lastp);

    const bool er0 = ml && b0 && b1;
    const bool er1 = b0 && b1 && b2;
    const bool er2 = b1 && b2 && b3;
    const bool er3 = b2 && b3 && mr;

    // ---- channel 0 ----
    float4 rA;
    rA.x = delem(al,   a4.x, a4.y, er0, e10, e20);
    rA.y = delem(a4.x, a4.y, a4.z, er1, e11, e21);
    rA.z = delem(a4.y, a4.z, a4.w, er2, e12, e22);
    rA.w = delem(a4.z, a4.w, ar,   er3, e13, e23);
    __stcs(reinterpret_cast<float4*>(out) + (base0 >> 2) + tid, rA);

    // ---- channel 1 ----
    float4 rC;
    rC.x = delem(cl,   c4.x, c4.y, er0, e10, e20);
    rC.y = delem(c4.x, c4.y, c4.z, er1, e11, e21);
    rC.z = delem(c4.y, c4.z, c4.w, er2, e12, e22);
    rC.w = delem(c4.z, c4.w, cr,   er3, e13, e23);
    __stcs(reinterpret_cast<float4*>(out) + (base1 >> 2) + tid, rC);
}

extern "C" void kernel_launch(void* const* d_in, const int* in_sizes, int n_in,
                              void* d_out, int out_size)
{
    const float* u    = (const float*)d_in[0];
    const float* mask = (const float*)d_in[1];
    float* o = (float*)d_out;

    const int nrows = 16 * HEIGHT;   // one block per (b, y) row
    dnet_kernel<<<nrows, NT>>>(u, mask, o);
}

// round 6
// speedup vs baseline: 1.0866x; 1.0679x over previous
#include <cuda_runtime.h>

// DerivativeNet forward, direction='x'
// u:    [B=16, C=2, H=1024, W=1024] float32
// mask: [B=16, 1,   H=1024, W=1024] float32 (0.0 / 1.0)
// out = eroded*central + edge1*forward + edge2*backward (zero-padded, h=0.01)
//
// edge1 = (cumsum==1)        == [first_set, second_set)
// edge2 = (cumsum==max)&mask == {last_set}
// Per element:  out = wp*u[i+1] + w0*u[i] + wm*u[i-1], weights shared by channels.

#define HEIGHT  1024
#define INV_H   100.0f
#define INV_2H  50.0f
#define NT      256
#define BIG     0x7fffffff

__global__ __launch_bounds__(NT, 6)
void dnet_kernel(const float* __restrict__ u,
                 const float* __restrict__ mask,
                 float* __restrict__ out)
{
    const int tid  = threadIdx.x;
    const int lane = tid & 31;
    const int wid  = tid >> 5;               // 0..7

    __shared__ int   wfs[8], wss[8], wls[8];             // per-warp first/second/last
    __shared__ int   em_last[8], em_first[8];            // warp-edge mask bits
    __shared__ float ea_last[8], ea_first[8];            // warp-edge u ch0
    __shared__ float ec_last[8], ec_first[8];            // warp-edge u ch1

    const unsigned row   = blockIdx.x;                   // b*HEIGHT + y
    const unsigned b     = row >> 10;
    const unsigned y     = row & (HEIGHT - 1);
    const unsigned base0 = ((b * 2u) << 20) | (y << 10); // u channel 0, elements
    const unsigned base1 = base0 + (1u << 20);           // u channel 1

    const float4* m4p = reinterpret_cast<const float4*>(mask) + ((row << 10) >> 2);
    const float4* a4p = reinterpret_cast<const float4*>(u) + (base0 >> 2);
    const float4* c4p = reinterpret_cast<const float4*>(u) + (base1 >> 2);

    // ---- 3 vector loads up front (MLP=3) ----
    const float4 m4 = m4p[tid];
    const float4 a4 = a4p[tid];
    const float4 c4 = c4p[tid];

    const int b0 = (m4.x != 0.0f), b1 = (m4.y != 0.0f),
              b2 = (m4.z != 0.0f), b3 = (m4.w != 0.0f);
    const int mbits = b0 | (b1 << 1) | (b2 << 2) | (b3 << 3);

    const unsigned full = 0xffffffffu;

    // ---- per-warp first/second/last set positions ----
    const unsigned nz  = __ballot_sync(full, mbits != 0);
    const unsigned nz2 = nz & (nz - 1);
    const int t1 = nz  ? (__ffs(nz)  - 1) : 0;
    const int t2 = nz2 ? (__ffs(nz2) - 1) : 0;
    const int tL = nz  ? (31 - __clz(nz)) : 0;
    const int mt1 = __shfl_sync(full, mbits, t1);
    const int mt2 = __shfl_sync(full, mbits, t2);
    const int mtL = __shfl_sync(full, mbits, tL);

    const int wbase = wid << 7;
    int wf = BIG, ws = BIG, wl = -1;
    if (nz) {
        wf = wbase + (t1 << 2) + (__ffs(mt1) - 1);
        const int m1b = mt1 & (mt1 - 1);
        if (m1b)      ws = wbase + (t1 << 2) + (__ffs(m1b) - 1);
        else if (nz2) ws = wbase + (t2 << 2) + (__ffs(mt2) - 1);
        wl = wbase + (tL << 2) + (31 - __clz(mtL));
    }

    // ---- in-warp halo exchange ----
    int   ml = __shfl_up_sync  (full, b3,   1);
    float al = __shfl_up_sync  (full, a4.w, 1);
    float cl = __shfl_up_sync  (full, c4.w, 1);
    int   mr = __shfl_down_sync(full, b0,   1);
    float ar = __shfl_down_sync(full, a4.x, 1);
    float cr = __shfl_down_sync(full, c4.x, 1);

    if (lane == 31) {
        wfs[wid] = wf; wss[wid] = ws; wls[wid] = wl;
        em_last[wid] = b3; ea_last[wid] = a4.w; ec_last[wid] = c4.w;
    }
    if (lane == 0) {
        em_first[wid] = b0; ea_first[wid] = a4.x; ec_first[wid] = c4.x;
    }
    __syncthreads();

    // ---- O(1) warp-parallel merge of the 8 per-warp index triples ----
    const int idx8 = lane & 7;
    const int a8 = wfs[idx8];                // broadcast LDS (4 lanes/addr)
    const int s8 = wss[idx8];
    const int l8 = wls[idx8];
    const unsigned has = __ballot_sync(full, (lane < 8) && (a8 != BIG));

    int f1 = BIG, f2 = BIG, lastp = -1;
    if (has) {                               // warp-uniform branch
        const int w1 = __ffs(has) - 1;
        f1 = __shfl_sync(full, a8, w1);
        const int s1 = __shfl_sync(full, s8, w1);
        const unsigned has2 = has & (has - 1);
        const int w2 = has2 ? (__ffs(has2) - 1) : 0;
        const int a2 = __shfl_sync(full, a8, w2);
        f2 = (s1 != BIG) ? s1 : (has2 ? a2 : BIG);
        const int wlw = 31 - __clz(has);
        lastp = __shfl_sync(full, l8, wlw);
    }

    // ---- fix halos at warp boundaries (zero padding at row ends) ----
    if (lane == 0) {
        if (wid > 0) { ml = em_last[wid-1]; al = ea_last[wid-1]; cl = ec_last[wid-1]; }
        else         { ml = 0; al = 0.0f; cl = 0.0f; }
    }
    if (lane == 31) {
        if (wid < 7) { mr = em_first[wid+1]; ar = ea_first[wid+1]; cr = ec_first[wid+1]; }
        else         { mr = 0; ar = 0.0f; cr = 0.0f; }
    }

    // ---- per-element weights (shared across channels) ----
    const int i0 = tid << 2;
    const unsigned du = (unsigned)(f2 - f1);
    const int j  = i0 - f1;                  // e1: (unsigned)(j+k) < du
    const int jl = lastp - i0;               // e2: k == jl

    float wp[4], w0[4], wm[4];
    {
        const int erb[4] = { ml && b0 && b1,  b0 && b1 && b2,
                             b1 && b2 && b3,  b2 && b3 && mr };
        #pragma unroll
        for (int k = 0; k < 4; k++) {
            const float fer = erb[k]                    ? INV_2H : 0.0f;
            const float fe1 = ((unsigned)(j + k) < du)  ? INV_H  : 0.0f;
            const float fe2 = (k == jl)                 ? INV_H  : 0.0f;
            wp[k] = fer + fe1;
            w0[k] = fe2 - fe1;
            wm[k] = -(fer + fe2);
        }
    }

    // ---- channel 0: 3 FMAs per element ----
    float4 rA;
    rA.x = fmaf(wp[0], a4.y, fmaf(w0[0], a4.x, wm[0] * al));
    rA.y = fmaf(wp[1], a4.z, fmaf(w0[1], a4.y, wm[1] * a4.x));
    rA.z = fmaf(wp[2], a4.w, fmaf(w0[2], a4.z, wm[2] * a4.y));
    rA.w = fmaf(wp[3], ar,   fmaf(w0[3], a4.w, wm[3] * a4.z));
    reinterpret_cast<float4*>(out)[(base0 >> 2) + tid] = rA;

    // ---- channel 1 ----
    float4 rC;
    rC.x = fmaf(wp[0], c4.y, fmaf(w0[0], c4.x, wm[0] * cl));
    rC.y = fmaf(wp[1], c4.z, fmaf(w0[1], c4.y, wm[1] * c4.x));
    rC.z = fmaf(wp[2], c4.w, fmaf(w0[2], c4.z, wm[2] * c4.y));
    rC.w = fmaf(wp[3], cr,   fmaf(w0[3], c4.w, wm[3] * c4.z));
    reinterpret_cast<float4*>(out)[(base1 >> 2) + tid] = rC;
}

extern "C" void kernel_launch(void* const* d_in, const int* in_sizes, int n_in,
                              void* d_out, int out_size)
{
    const float* u    = (const float*)d_in[0];
    const float* mask = (const float*)d_in[1];
    float* o = (float*)d_out;

    const int nrows = 16 * HEIGHT;   // one block per (b, y) row
    dnet_kernel<<<nrows, NT>>>(u, mask, o);
}